// round 1
// baseline (speedup 1.0000x reference)
#include <cuda_runtime.h>

// out[c, i, j, k, l] = tb[c,0,i] * tb[c,1,j] * tb[c,2,k] * tb[c,3,l]
// where tb = tensor + bias, shapes (C, 4, 16). Output (C, 16,16,16,16).
//
// Pure store-bandwidth kernel: 512 MB of fp32 output, ~1 MB input.
// One CTA per c; 256 threads; each thread writes 64 float4 (1 KB), with
// lane-adjacent float4 addresses => fully coalesced STG.E.128 streams.

static constexpr int LDIM = 16;        // L
static constexpr int NFAC = 4;         // N factors
static constexpr int THREADS = 256;

__global__ __launch_bounds__(THREADS)
void tpe_kernel(const float* __restrict__ tensor,
                const float* __restrict__ bias,
                float4* __restrict__ out)
{
    __shared__ float s[NFAC * LDIM];   // 64 floats: tb rows for this c

    const int c = blockIdx.x;
    const int t = threadIdx.x;

    // Load tb = tensor + bias for this channel into shared.
    if (t < NFAC * LDIM) {
        const int g = c * (NFAC * LDIM) + t;
        s[t] = tensor[g] + bias[g];
    }
    __syncthreads();

    const float* s0 = s;               // factor over i
    const float* s1 = s + LDIM;        // factor over j
    const float* s2 = s + 2 * LDIM;    // factor over k
    const float* s3 = s + 3 * LDIM;    // factor over l

    // float4 linear index within channel: q in [0, 16384), q = t + 256*it.
    // element index e = 4q:
    //   l = e & 15          -> l-group lg = q & 3       (fixed per thread)
    //   k = (e>>4)  & 15    -> k = (q>>2) & 15          (fixed per thread)
    //   j = (e>>8)  & 15    -> j = (q>>6) & 15 = jlow | ((it&3)<<2)
    //   i = (e>>12) & 15    -> i = it >> 2
    const int lg   = t & 3;
    const int k    = (t >> 2) & 15;
    const int jlow = (t >> 6) & 3;

    const float p2 = s2[k];
    const float4 v3 = make_float4(s3[lg * 4 + 0], s3[lg * 4 + 1],
                                  s3[lg * 4 + 2], s3[lg * 4 + 3]);

    float4* ob = out + (size_t)c * 16384 + t;

    #pragma unroll
    for (int i = 0; i < 16; ++i) {
        const float a0 = s0[i] * p2;
        #pragma unroll
        for (int jj = 0; jj < 4; ++jj) {
            const float a = a0 * s1[jlow + (jj << 2)];
            const int it = (i << 2) + jj;
            float4 v;
            v.x = a * v3.x;
            v.y = a * v3.y;
            v.z = a * v3.z;
            v.w = a * v3.w;
            ob[it * 256] = v;
        }
    }
}

extern "C" void kernel_launch(void* const* d_in, const int* in_sizes, int n_in,
                              void* d_out, int out_size)
{
    const float* tensor = (const float*)d_in[0];
    const float* bias   = (const float*)d_in[1];
    float4* out         = (float4*)d_out;

    const int C = in_sizes[0] / (NFAC * LDIM);   // 2048

    tpe_kernel<<<C, THREADS>>>(tensor, bias, out);
}